// round 16
// baseline (speedup 1.0000x reference)
#include <cuda_runtime.h>
#include <cuda_bf16.h>
#include <cstdint>

#define SEQ   512
#define BATCH 128
#define DIN   512
#define DH    1024
#define DOUT  256
#define WROW  (DIN + DH)   // 1536
#define MTOT  (SEQ * BATCH)  // 65536

#define NBLK   128
#define NTHR   512          // k_rnn: 16 warps
#define KSPLIT 8
#define KSL    128
#define JT     64

// ---- SMEM layout for k_rnn (bytes) ----
#define SWF_OFF    0
#define SWF_BYTES  32768
#define SH_OFF     32768
#define SH_STRIDE  576
#define SMEM_RNN   (SWF_BYTES + BATCH * SH_STRIDE)   // 106496 B

// ---- SMEM layout for k_xw_mma (3-stage, fragment-ordered staging) ----
#define XROW_B     192
#define XARR_B     (128 * XROW_B)           // 24576
#define XBUF_B     (2 * XARR_B)             // 49152
#define SMEM_XW    (3 * XBUF_B)             // 147456

// Device-global scratch
__device__ float    g_xW[SEQ * BATCH * DH];
__device__ float    g_H[BATCH * DH];
__device__ uint32_t g_H2[BATCH * 1024];
__device__ float    g_Cpart[KSPLIT * BATCH * DH];
__device__ uint32_t g_A2[(long)MTOT * 512];
__device__ uint32_t g_B2[DH * 512];
__device__ unsigned g_flags[NBLK];          // per-block generation flags

// ---------------- helpers ----------------
__device__ __forceinline__ uint32_t bf16pair(float e0, float e1) {
    __nv_bfloat162 p = __floats2bfloat162_rn(e0, e1);
    return *(uint32_t*)&p;
}
__device__ __forceinline__ float bf16of(float x) {
    return __bfloat162float(__float2bfloat16(x));
}
__device__ __forceinline__ void mma16(float* d,
                                      uint32_t a0, uint32_t a1, uint32_t a2, uint32_t a3,
                                      uint32_t b0, uint32_t b1) {
    asm volatile(
        "mma.sync.aligned.m16n8k16.row.col.f32.bf16.bf16.f32 "
        "{%0,%1,%2,%3}, {%4,%5,%6,%7}, {%8,%9}, {%0,%1,%2,%3};"
        : "+f"(d[0]), "+f"(d[1]), "+f"(d[2]), "+f"(d[3])
        : "r"(a0), "r"(a1), "r"(a2), "r"(a3), "r"(b0), "r"(b1));
}
__device__ __forceinline__ void cpasync16(void* smem_dst, const void* gsrc) {
    uint32_t d = (uint32_t)__cvta_generic_to_shared(smem_dst);
    asm volatile("cp.async.cg.shared.global [%0], [%1], 16;"
                 :: "r"(d), "l"(gsrc) : "memory");
}
__device__ __forceinline__ int frag_slot(int j) {
    return (j >> 4) * 16 + (((j & 7) >> 1) << 2) + (((j >> 3) & 1) << 1);
}

// ---------------------------------------------------------------------------
__global__ void k_init(const float* __restrict__ hidden)
{
    int i = blockIdx.x * blockDim.x + threadIdx.x;
    if (i < BATCH * DH) g_H[i] = hidden[i];
    if (i < BATCH * DH / 2) {
        int b = i >> 9;
        int j = (i & 511) << 1;
        float x0 = hidden[b * DH + j];
        float x1 = hidden[b * DH + j + 1];
        float h0 = bf16of(x0), h1 = bf16of(x1);
        int o = frag_slot(j);
        g_H2[b * 1024 + o]     = bf16pair(h0, h1);
        g_H2[b * 1024 + o + 1] = bf16pair(x0 - h0, x1 - h1);
    }
    if (i < NBLK) g_flags[i] = 0;
}

// ---------------------------------------------------------------------------
#define A_PAIRS ((long)MTOT * 256)
__global__ void k_prep(const float* __restrict__ x, const float* __restrict__ W)
{
    long i = (long)blockIdx.x * blockDim.x + threadIdx.x;
    if (i < A_PAIRS) {
        long m = i >> 8;
        int  j = (int)(i & 255) << 1;
        float v0 = x[m * 512 + j], v1 = x[m * 512 + j + 1];
        float h0 = bf16of(v0), h1 = bf16of(v1);
        int o = frag_slot(j);
        g_A2[m * 512 + o]     = bf16pair(h0, h1);
        g_A2[m * 512 + o + 1] = bf16pair(v0 - h0, v1 - h1);
    } else {
        long ib = i - A_PAIRS;
        if (ib < (long)DH * 256) {
            int n = (int)(ib >> 8);
            int j = (int)(ib & 255) << 1;
            float v0 = W[n * WROW + j], v1 = W[n * WROW + j + 1];
            float h0 = bf16of(v0), h1 = bf16of(v1);
            int o = frag_slot(j);
            g_B2[n * 512 + o]     = bf16pair(h0, h1);
            g_B2[n * 512 + o + 1] = bf16pair(v0 - h0, v1 - h1);
        }
    }
}

// ---------------------------------------------------------------------------
// xW = x @ Wx, bf16x3 m16n8k16, 3-stage cp.async pipeline, ONE sync per iter.
// ---------------------------------------------------------------------------
__global__ void __launch_bounds__(256) k_xw_mma()
{
    extern __shared__ char smem[];

    const int tid  = threadIdx.x;
    const int n0   = blockIdx.x << 7;
    const int m0   = blockIdx.y << 7;
    const int wrp  = tid >> 5;
    const int lane = tid & 31;
    const int g    = lane >> 2;
    const int tq   = lane & 3;
    const int wm   = wrp & 3;
    const int wn   = wrp >> 2;

    auto issue = [&](int cb) {
        char* base = smem + (cb % 3) * XBUF_B;
        #pragma unroll
        for (int it = 0; it < 8; ++it) {
            int p   = tid + it * 256;
            int arr = p >> 10;
            int rem = p & 1023;
            int row = rem >> 3;
            int seg = rem & 7;
            char* dst = base + arr * XARR_B + row * XROW_B + seg * 16;
            const uint32_t* src = arr == 0
                ? &g_A2[(long)(m0 + row) * 512 + cb * 32 + seg * 4]
                : &g_B2[(long)(n0 + row) * 512 + cb * 32 + seg * 4];
            cpasync16(dst, src);
        }
        asm volatile("cp.async.commit_group;" ::: "memory");
    };

    float acc[2][8][4];
    #pragma unroll
    for (int mf = 0; mf < 2; ++mf)
        #pragma unroll
        for (int nf = 0; nf < 8; ++nf)
            #pragma unroll
            for (int c = 0; c < 4; ++c) acc[mf][nf][c] = 0.f;

    issue(0);
    issue(1);

    for (int cb = 0; cb < 16; ++cb) {
        asm volatile("cp.async.wait_group 1;" ::: "memory");
        __syncthreads();
        if (cb + 2 < 16) issue(cb + 2);

        const char* sA = smem + (cb % 3) * XBUF_B;
        const char* sB = sA + XARR_B;

        #pragma unroll
        for (int kc = 0; kc < 2; ++kc) {
            uint4 U0[2], U1[2];
            #pragma unroll
            for (int mf = 0; mf < 2; ++mf) {
                int r0 = wm * 32 + mf * 16 + g;
                U0[mf] = *(const uint4*)(sA + r0 * XROW_B + kc * 64 + tq * 16);
                U1[mf] = *(const uint4*)(sA + (r0 + 8) * XROW_B + kc * 64 + tq * 16);
            }
            #pragma unroll
            for (int nf = 0; nf < 8; ++nf) {
                int nr = wn * 64 + nf * 8 + g;
                uint4 V = *(const uint4*)(sB + nr * XROW_B + kc * 64 + tq * 16);
                #pragma unroll
                for (int mf = 0; mf < 2; ++mf) {
                    mma16(acc[mf][nf], U0[mf].x, U1[mf].x, U0[mf].z, U1[mf].z, V.x, V.z);
                    mma16(acc[mf][nf], U0[mf].y, U1[mf].y, U0[mf].w, U1[mf].w, V.x, V.z);
                    mma16(acc[mf][nf], U0[mf].x, U1[mf].x, U0[mf].z, U1[mf].z, V.y, V.w);
                }
            }
        }
    }

    #pragma unroll
    for (int mf = 0; mf < 2; ++mf) {
        int r0 = m0 + wm * 32 + mf * 16 + g;
        #pragma unroll
        for (int nf = 0; nf < 8; ++nf) {
            int c = n0 + wn * 64 + nf * 8 + (tq << 1);
            *(float2*)&g_xW[(long)r0 * DH + c]       = make_float2(acc[mf][nf][0], acc[mf][nf][1]);
            *(float2*)&g_xW[(long)(r0 + 8) * DH + c] = make_float2(acc[mf][nf][2], acc[mf][nf][3]);
        }
    }
}

// ---------------------------------------------------------------------------
// Flag-array grid barrier: per-block generation flags, no central atomic.
// Arrive = one st.release.gpu (parallel across blocks). Wait = 128 threads
// spin on distinct flags with ld.relaxed.gpu (L2, never stale), then
// fence.acq_rel.gpu + __syncthreads for full happens-before transitivity.
// ---------------------------------------------------------------------------
__device__ __forceinline__ void grid_barrier(unsigned& gen)
{
    __syncthreads();
    gen += 1;
    if (threadIdx.x == 0) {
        asm volatile("st.release.gpu.global.u32 [%0], %1;"
                     :: "l"(&g_flags[blockIdx.x]), "r"(gen) : "memory");
    }
    if (threadIdx.x < NBLK) {
        unsigned f;
        do {
            asm volatile("ld.relaxed.gpu.global.u32 %0, [%1];"
                         : "=r"(f) : "l"(&g_flags[threadIdx.x]) : "memory");
        } while (f < gen);
        asm volatile("fence.acq_rel.gpu;" ::: "memory");
    }
    __syncthreads();
}

// ---------------------------------------------------------------------------
// Persistent recurrence: 512 threads, 4-chunk pipelined H copy, flag barriers.
// ---------------------------------------------------------------------------
__global__ void __launch_bounds__(NTHR, 1) k_rnn(
    const float* __restrict__ Wi2h, const float* __restrict__ bi2h,
    const float* __restrict__ Wh2o, const float* __restrict__ bh2o,
    float* __restrict__ out, int out_size)
{
    extern __shared__ char smem[];
    const uint4* sWf = (const uint4*)(smem + SWF_OFF);

    const int tid    = threadIdx.x;
    const int blk    = blockIdx.x;
    const int jx     = blk & 15;
    const int kx     = blk >> 4;
    const int j0     = jx * JT;
    const int k0     = kx * KSL;
    const int wrp    = tid >> 5;
    const int lane   = tid & 31;
    const int g      = lane >> 2;
    const int tq     = lane & 3;
    const int brow   = (wrp & 7) * 16 + g;
    const int nthalf = wrp >> 3;

    for (int p = tid; p < 8 * 8 * 32; p += NTHR) {
        int kc = p >> 8;
        int nt = (p >> 5) & 7;
        int ln = p & 31;
        int t  = ln & 3;
        int n  = j0 + nt * 8 + (ln >> 2);
        const float* wrow = &Wi2h[n * WROW + DIN + k0 + kc * 16];
        float w0 = wrow[2*t],     w1 = wrow[2*t + 1];
        float w2 = wrow[2*t + 8], w3 = wrow[2*t + 9];
        float h0 = bf16of(w0), h1 = bf16of(w1), h2 = bf16of(w2), h3 = bf16of(w3);
        uint4 frag;
        frag.x = bf16pair(h0, h1);
        frag.y = bf16pair(h2, h3);
        frag.z = bf16pair(w0 - h0, w1 - h1);
        frag.w = bf16pair(w2 - h2, w3 - h3);
        ((uint4*)(smem + SWF_OFF))[p] = frag;
    }

    unsigned gen = 0;
    const int gtid = blk * NTHR + tid;
    const float2* Cp2 = (const float2*)g_Cpart;
    const float2* xW2 = (const float2*)g_xW;
    const int pj = (gtid << 1) & (DH - 1);
    const float2 bias = make_float2(bi2h[pj], bi2h[pj + 1]);

    float* part_row0 = &g_Cpart[kx * (BATCH * DH) + brow * DH + j0 +
                                nthalf * 32 + (tq << 1)];

    const int h2r = gtid >> 9;
    uint32_t* h2w = &g_H2[h2r * 1024 + frag_slot(pj)];

    const char* h2src = (const char*)g_H2 + (size_t)kx * 512;

    for (int t = 0; t < SEQ; ++t) {
        // ---- issue H copy as 4 chunks of 16 KB (kc pairs) ----
        #pragma unroll
        for (int q = 0; q < 4; ++q) {
            #pragma unroll
            for (int it = 0; it < 2; ++it) {
                int p   = tid + it * NTHR;
                int r   = p >> 3;
                int c16 = (p & 7) + q * 8;
                uint32_t dst = (uint32_t)__cvta_generic_to_shared(
                    smem + SH_OFF + r * SH_STRIDE + c16 * 16);
                const char* src = h2src + (size_t)r * 4096 + c16 * 16;
                asm volatile("cp.async.cg.shared.global [%0], [%1], 16;"
                             :: "r"(dst), "l"(src) : "memory");
            }
            asm volatile("cp.async.commit_group;" ::: "memory");
        }

        // prefetch xW (DRAM) while copies fly
        float2 xw_pre = __ldg(&xW2[(size_t)t * 65536 + gtid]);

        float acc[4][4];
        #pragma unroll
        for (int nt = 0; nt < 4; ++nt)
            #pragma unroll
            for (int c = 0; c < 4; ++c) acc[nt][c] = 0.f;

        // ---- MMA interleaved with chunk arrivals ----
        #pragma unroll
        for (int q = 0; q < 4; ++q) {
            if (q == 0)      asm volatile("cp.async.wait_group 3;" ::: "memory");
            else if (q == 1) asm volatile("cp.async.wait_group 2;" ::: "memory");
            else if (q == 2) asm volatile("cp.async.wait_group 1;" ::: "memory");
            else             asm volatile("cp.async.wait_group 0;" ::: "memory");
            __syncthreads();
            #pragma unroll
            for (int kk = 0; kk < 2; ++kk) {
                int kc = q * 2 + kk;
                uint4 U0 = *(const uint4*)(smem + SH_OFF + brow * SH_STRIDE + kc * 64 + tq * 16);
                uint4 U1 = *(const uint4*)(smem + SH_OFF + (brow + 8) * SH_STRIDE + kc * 64 + tq * 16);
                #pragma unroll
                for (int np = 0; np < 4; ++np) {
                    uint4 bf = sWf[((kc << 3) + nthalf * 4 + np) * 32 + lane];
                    mma16(acc[np], U0.x, U1.x, U0.z, U1.z, bf.x, bf.y);
                    mma16(acc[np], U0.y, U1.y, U0.w, U1.w, bf.x, bf.y);
                    mma16(acc[np], U0.x, U1.x, U0.z, U1.z, bf.z, bf.w);
                }
            }
        }

        #pragma unroll
        for (int np = 0; np < 4; ++np) {
            *(float2*)(part_row0 + np * 8)          = make_float2(acc[np][0], acc[np][1]);
            *(float2*)(part_row0 + 8 * DH + np * 8) = make_float2(acc[np][2], acc[np][3]);
        }

        grid_barrier(gen);

        // ---- phase 2: reduce 8 partials + xW + bias, tanh -> g_H2 ----
        {
            float2 s = Cp2[gtid];
            #pragma unroll
            for (int sp = 1; sp < KSPLIT; ++sp) {
                float2 c = Cp2[sp * 65536 + gtid];
                s.x += c.x; s.y += c.y;
            }
            float rx = tanhf(s.x + xw_pre.x + bias.x);
            float ry = tanhf(s.y + xw_pre.y + bias.y);

            float hx = bf16of(rx), hy = bf16of(ry);
            h2w[0] = bf16pair(hx, hy);
            h2w[1] = bf16pair(rx - hx, ry - hy);

            if (t == SEQ - 1) ((float2*)g_H)[gtid] = make_float2(rx, ry);
        }

        grid_barrier(gen);
    }

    // ------------------- Epilogue: logits + softmax -------------------
    {
        float* sv   = (float*)smem;
        float* sred = (float*)smem + 1024;
        const int b = blk;

        if (tid < 256)
            ((float4*)sv)[tid] = *(const float4*)&g_H[b * DH + (tid << 2)];
        __syncthreads();

        float logit = 0.f, e = 0.f;
        if (tid < 256) {
            float acc = 0.f;
            const float4* wr = (const float4*)(Wh2o + tid * DH);
            #pragma unroll 8
            for (int qq = 0; qq < DH / 4; ++qq) {
                float4 w = wr[qq];
                float4 h = ((const float4*)sv)[qq];
                acc += w.x * h.x + w.y * h.y + w.z * h.z + w.w * h.w;
            }
            logit = acc + bh2o[tid];
            sred[tid] = logit;
        }
        __syncthreads();
        for (int s = 128; s > 0; s >>= 1) {
            if (tid < s) sred[tid] = fmaxf(sred[tid], sred[tid + s]);
            __syncthreads();
        }
        float mx = sred[0];
        __syncthreads();
        if (tid < 256) {
            e = expf(logit - mx);
            sred[tid] = e;
        }
        __syncthreads();
        for (int s = 128; s > 0; s >>= 1) {
            if (tid < s) sred[tid] += sred[tid + s];
            __syncthreads();
        }
        if (tid < 256) {
            float inv = 1.f / sred[0];
            out[b * DOUT + tid] = e * inv;
        }
    }

    if (out_size >= BATCH * DOUT + BATCH * DH) {
        for (int i = gtid; i < BATCH * DH; i += NBLK * NTHR)
            out[BATCH * DOUT + i] = g_H[i];
    }
}

// ---------------------------------------------------------------------------
extern "C" void kernel_launch(void* const* d_in, const int* in_sizes, int n_in,
                              void* d_out, int out_size)
{
    const float* x      = (const float*)d_in[0];
    const float* hidden = (const float*)d_in[1];
    const float* Wi2h   = (const float*)d_in[2];
    const float* bi2h   = (const float*)d_in[3];
    const float* Wh2o   = (const float*)d_in[4];
    const float* bh2o   = (const float*)d_in[5];
    float* out = (float*)d_out;

    cudaFuncSetAttribute(k_rnn, cudaFuncAttributeMaxDynamicSharedMemorySize,
                         SMEM_RNN);
    cudaFuncSetAttribute(k_xw_mma, cudaFuncAttributeMaxDynamicSharedMemorySize,
                         SMEM_XW);

    k_init<<<512, 256>>>(hidden);

    long prep_items = A_PAIRS + (long)DH * 256;
    k_prep<<<(int)((prep_items + 255) / 256), 256>>>(x, Wi2h);

    dim3 gx(DH / 128, MTOT / 128);   // (8, 512)
    k_xw_mma<<<gx, 256, SMEM_XW>>>();

    k_rnn<<<NBLK, NTHR, SMEM_RNN>>>(Wi2h, bi2h, Wh2o, bh2o, out, out_size);
}

// round 17
// speedup vs baseline: 1.5379x; 1.5379x over previous
#include <cuda_runtime.h>
#include <cuda_bf16.h>
#include <cstdint>

#define SEQ   512
#define BATCH 128
#define DIN   512
#define DH    1024
#define DOUT  256
#define WROW  (DIN + DH)   // 1536
#define MTOT  (SEQ * BATCH)  // 65536

#define NBLK   128
#define NTHR   512          // k_rnn: 16 warps
#define KSPLIT 8
#define KSL    128
#define JT     64

// ---- SMEM layout for k_rnn (bytes) ----
#define SWF_OFF    0
#define SWF_BYTES  32768
#define SH_OFF     32768
#define SH_STRIDE  576
#define SMEM_RNN   (SWF_BYTES + BATCH * SH_STRIDE)   // 106496 B

// ---- SMEM layout for k_xw_mma (3-stage, fragment-ordered staging) ----
#define XROW_B     192
#define XARR_B     (128 * XROW_B)           // 24576
#define XBUF_B     (2 * XARR_B)             // 49152
#define SMEM_XW    (3 * XBUF_B)             // 147456

// Device-global scratch
__device__ float    g_xW[SEQ * BATCH * DH];
__device__ float    g_H[BATCH * DH];
__device__ uint32_t g_H2[BATCH * 1024];
__device__ float    g_Cpart[KSPLIT * BATCH * DH];
__device__ uint32_t g_A2[(long)MTOT * 512];
__device__ uint32_t g_B2[DH * 512];
// Tree barrier state: 16 leaves (padded to 128B lines), 1 root, 1 flag.
__device__ unsigned g_leaf[16 * 32];
__device__ unsigned g_root;
__device__ unsigned g_bflag;

// ---------------- helpers ----------------
__device__ __forceinline__ uint32_t bf16pair(float e0, float e1) {
    __nv_bfloat162 p = __floats2bfloat162_rn(e0, e1);
    return *(uint32_t*)&p;
}
__device__ __forceinline__ float bf16of(float x) {
    return __bfloat162float(__float2bfloat16(x));
}
__device__ __forceinline__ void mma16(float* d,
                                      uint32_t a0, uint32_t a1, uint32_t a2, uint32_t a3,
                                      uint32_t b0, uint32_t b1) {
    asm volatile(
        "mma.sync.aligned.m16n8k16.row.col.f32.bf16.bf16.f32 "
        "{%0,%1,%2,%3}, {%4,%5,%6,%7}, {%8,%9}, {%0,%1,%2,%3};"
        : "+f"(d[0]), "+f"(d[1]), "+f"(d[2]), "+f"(d[3])
        : "r"(a0), "r"(a1), "r"(a2), "r"(a3), "r"(b0), "r"(b1));
}
__device__ __forceinline__ void cpasync16(void* smem_dst, const void* gsrc) {
    uint32_t d = (uint32_t)__cvta_generic_to_shared(smem_dst);
    asm volatile("cp.async.cg.shared.global [%0], [%1], 16;"
                 :: "r"(d), "l"(gsrc) : "memory");
}
__device__ __forceinline__ int frag_slot(int j) {
    return (j >> 4) * 16 + (((j & 7) >> 1) << 2) + (((j >> 3) & 1) << 1);
}

// ---------------------------------------------------------------------------
__global__ void k_init(const float* __restrict__ hidden)
{
    int i = blockIdx.x * blockDim.x + threadIdx.x;
    if (i < BATCH * DH) g_H[i] = hidden[i];
    if (i < BATCH * DH / 2) {
        int b = i >> 9;
        int j = (i & 511) << 1;
        float x0 = hidden[b * DH + j];
        float x1 = hidden[b * DH + j + 1];
        float h0 = bf16of(x0), h1 = bf16of(x1);
        int o = frag_slot(j);
        g_H2[b * 1024 + o]     = bf16pair(h0, h1);
        g_H2[b * 1024 + o + 1] = bf16pair(x0 - h0, x1 - h1);
    }
    if (i < 16 * 32) g_leaf[i] = 0;
    if (i == 0) { g_root = 0; g_bflag = 0; }
}

// ---------------------------------------------------------------------------
#define A_PAIRS ((long)MTOT * 256)
__global__ void k_prep(const float* __restrict__ x, const float* __restrict__ W)
{
    long i = (long)blockIdx.x * blockDim.x + threadIdx.x;
    if (i < A_PAIRS) {
        long m = i >> 8;
        int  j = (int)(i & 255) << 1;
        float v0 = x[m * 512 + j], v1 = x[m * 512 + j + 1];
        float h0 = bf16of(v0), h1 = bf16of(v1);
        int o = frag_slot(j);
        g_A2[m * 512 + o]     = bf16pair(h0, h1);
        g_A2[m * 512 + o + 1] = bf16pair(v0 - h0, v1 - h1);
    } else {
        long ib = i - A_PAIRS;
        if (ib < (long)DH * 256) {
            int n = (int)(ib >> 8);
            int j = (int)(ib & 255) << 1;
            float v0 = W[n * WROW + j], v1 = W[n * WROW + j + 1];
            float h0 = bf16of(v0), h1 = bf16of(v1);
            int o = frag_slot(j);
            g_B2[n * 512 + o]     = bf16pair(h0, h1);
            g_B2[n * 512 + o + 1] = bf16pair(v0 - h0, v1 - h1);
        }
    }
}

// ---------------------------------------------------------------------------
// xW = x @ Wx, bf16x3 m16n8k16, 3-stage cp.async pipeline, ONE sync per iter.
// ---------------------------------------------------------------------------
__global__ void __launch_bounds__(256) k_xw_mma()
{
    extern __shared__ char smem[];

    const int tid  = threadIdx.x;
    const int n0   = blockIdx.x << 7;
    const int m0   = blockIdx.y << 7;
    const int wrp  = tid >> 5;
    const int lane = tid & 31;
    const int g    = lane >> 2;
    const int tq   = lane & 3;
    const int wm   = wrp & 3;
    const int wn   = wrp >> 2;

    auto issue = [&](int cb) {
        char* base = smem + (cb % 3) * XBUF_B;
        #pragma unroll
        for (int it = 0; it < 8; ++it) {
            int p   = tid + it * 256;
            int arr = p >> 10;
            int rem = p & 1023;
            int row = rem >> 3;
            int seg = rem & 7;
            char* dst = base + arr * XARR_B + row * XROW_B + seg * 16;
            const uint32_t* src = arr == 0
                ? &g_A2[(long)(m0 + row) * 512 + cb * 32 + seg * 4]
                : &g_B2[(long)(n0 + row) * 512 + cb * 32 + seg * 4];
            cpasync16(dst, src);
        }
        asm volatile("cp.async.commit_group;" ::: "memory");
    };

    float acc[2][8][4];
    #pragma unroll
    for (int mf = 0; mf < 2; ++mf)
        #pragma unroll
        for (int nf = 0; nf < 8; ++nf)
            #pragma unroll
            for (int c = 0; c < 4; ++c) acc[mf][nf][c] = 0.f;

    issue(0);
    issue(1);

    for (int cb = 0; cb < 16; ++cb) {
        asm volatile("cp.async.wait_group 1;" ::: "memory");
        __syncthreads();
        if (cb + 2 < 16) issue(cb + 2);

        const char* sA = smem + (cb % 3) * XBUF_B;
        const char* sB = sA + XARR_B;

        #pragma unroll
        for (int kc = 0; kc < 2; ++kc) {
            uint4 U0[2], U1[2];
            #pragma unroll
            for (int mf = 0; mf < 2; ++mf) {
                int r0 = wm * 32 + mf * 16 + g;
                U0[mf] = *(const uint4*)(sA + r0 * XROW_B + kc * 64 + tq * 16);
                U1[mf] = *(const uint4*)(sA + (r0 + 8) * XROW_B + kc * 64 + tq * 16);
            }
            #pragma unroll
            for (int nf = 0; nf < 8; ++nf) {
                int nr = wn * 64 + nf * 8 + g;
                uint4 V = *(const uint4*)(sB + nr * XROW_B + kc * 64 + tq * 16);
                #pragma unroll
                for (int mf = 0; mf < 2; ++mf) {
                    mma16(acc[mf][nf], U0[mf].x, U1[mf].x, U0[mf].z, U1[mf].z, V.x, V.z);
                    mma16(acc[mf][nf], U0[mf].y, U1[mf].y, U0[mf].w, U1[mf].w, V.x, V.z);
                    mma16(acc[mf][nf], U0[mf].x, U1[mf].x, U0[mf].z, U1[mf].z, V.y, V.w);
                }
            }
        }
    }

    #pragma unroll
    for (int mf = 0; mf < 2; ++mf) {
        int r0 = m0 + wm * 32 + mf * 16 + g;
        #pragma unroll
        for (int nf = 0; nf < 8; ++nf) {
            int c = n0 + wn * 64 + nf * 8 + (tq << 1);
            *(float2*)&g_xW[(long)r0 * DH + c]       = make_float2(acc[mf][nf][0], acc[mf][nf][1]);
            *(float2*)&g_xW[(long)(r0 + 8) * DH + c] = make_float2(acc[mf][nf][2], acc[mf][nf][3]);
        }
    }
}

// ---------------------------------------------------------------------------
// Two-level tree grid barrier. ONE arriving/spinning thread per block
// (the R16 lesson: spin population must stay at 1/block). Monotonic
// counters — no resets, no reset races. acq_rel RMW chains + release
// flag + acquire spin give full transitivity.
// ---------------------------------------------------------------------------
__device__ __forceinline__ void grid_barrier(unsigned& gen)
{
    __syncthreads();
    if (threadIdx.x == 0) {
        gen += 1;
        unsigned leaf = (blockIdx.x & 15) * 32;
        unsigned a;
        asm volatile("atom.acq_rel.gpu.global.add.u32 %0, [%1], 1;"
                     : "=r"(a) : "l"(&g_leaf[leaf]) : "memory");
        bool done = false;
        if (a == gen * 8u - 1u) {                 // last of 8 in this leaf
            unsigned b;
            asm volatile("atom.acq_rel.gpu.global.add.u32 %0, [%1], 1;"
                         : "=r"(b) : "l"(&g_root) : "memory");
            if (b == gen * 16u - 1u) {            // last leaf overall
                asm volatile("st.release.gpu.global.u32 [%0], %1;"
                             :: "l"(&g_bflag), "r"(gen) : "memory");
                done = true;
            }
        }
        if (!done) {
            unsigned f;
            do {
                asm volatile("ld.acquire.gpu.global.u32 %0, [%1];"
                             : "=r"(f) : "l"(&g_bflag) : "memory");
            } while (f < gen);
        }
    } else {
        gen += 1;
    }
    __syncthreads();
}

// ---------------------------------------------------------------------------
// Persistent recurrence: 512 threads, 4-chunk pipelined H copy, tree barriers.
// ---------------------------------------------------------------------------
__global__ void __launch_bounds__(NTHR, 1) k_rnn(
    const float* __restrict__ Wi2h, const float* __restrict__ bi2h,
    const float* __restrict__ Wh2o, const float* __restrict__ bh2o,
    float* __restrict__ out, int out_size)
{
    extern __shared__ char smem[];
    const uint4* sWf = (const uint4*)(smem + SWF_OFF);

    const int tid    = threadIdx.x;
    const int blk    = blockIdx.x;
    const int jx     = blk & 15;
    const int kx     = blk >> 4;
    const int j0     = jx * JT;
    const int k0     = kx * KSL;
    const int wrp    = tid >> 5;
    const int lane   = tid & 31;
    const int g      = lane >> 2;
    const int tq     = lane & 3;
    const int brow   = (wrp & 7) * 16 + g;
    const int nthalf = wrp >> 3;

    for (int p = tid; p < 8 * 8 * 32; p += NTHR) {
        int kc = p >> 8;
        int nt = (p >> 5) & 7;
        int ln = p & 31;
        int t  = ln & 3;
        int n  = j0 + nt * 8 + (ln >> 2);
        const float* wrow = &Wi2h[n * WROW + DIN + k0 + kc * 16];
        float w0 = wrow[2*t],     w1 = wrow[2*t + 1];
        float w2 = wrow[2*t + 8], w3 = wrow[2*t + 9];
        float h0 = bf16of(w0), h1 = bf16of(w1), h2 = bf16of(w2), h3 = bf16of(w3);
        uint4 frag;
        frag.x = bf16pair(h0, h1);
        frag.y = bf16pair(h2, h3);
        frag.z = bf16pair(w0 - h0, w1 - h1);
        frag.w = bf16pair(w2 - h2, w3 - h3);
        ((uint4*)(smem + SWF_OFF))[p] = frag;
    }

    unsigned gen = 0;
    const int gtid = blk * NTHR + tid;
    const float2* Cp2 = (const float2*)g_Cpart;
    const float2* xW2 = (const float2*)g_xW;
    const int pj = (gtid << 1) & (DH - 1);
    const float2 bias = make_float2(bi2h[pj], bi2h[pj + 1]);

    float* part_row0 = &g_Cpart[kx * (BATCH * DH) + brow * DH + j0 +
                                nthalf * 32 + (tq << 1)];

    const int h2r = gtid >> 9;
    uint32_t* h2w = &g_H2[h2r * 1024 + frag_slot(pj)];

    const char* h2src = (const char*)g_H2 + (size_t)kx * 512;

    for (int t = 0; t < SEQ; ++t) {
        // ---- issue H copy as 4 chunks of 16 KB (kc pairs) ----
        #pragma unroll
        for (int q = 0; q < 4; ++q) {
            #pragma unroll
            for (int it = 0; it < 2; ++it) {
                int p   = tid + it * NTHR;
                int r   = p >> 3;
                int c16 = (p & 7) + q * 8;
                uint32_t dst = (uint32_t)__cvta_generic_to_shared(
                    smem + SH_OFF + r * SH_STRIDE + c16 * 16);
                const char* src = h2src + (size_t)r * 4096 + c16 * 16;
                asm volatile("cp.async.cg.shared.global [%0], [%1], 16;"
                             :: "r"(dst), "l"(src) : "memory");
            }
            asm volatile("cp.async.commit_group;" ::: "memory");
        }

        // prefetch xW (DRAM) while copies fly
        float2 xw_pre = __ldg(&xW2[(size_t)t * 65536 + gtid]);

        float acc[4][4];
        #pragma unroll
        for (int nt = 0; nt < 4; ++nt)
            #pragma unroll
            for (int c = 0; c < 4; ++c) acc[nt][c] = 0.f;

        // ---- MMA interleaved with chunk arrivals ----
        #pragma unroll
        for (int q = 0; q < 4; ++q) {
            if (q == 0)      asm volatile("cp.async.wait_group 3;" ::: "memory");
            else if (q == 1) asm volatile("cp.async.wait_group 2;" ::: "memory");
            else if (q == 2) asm volatile("cp.async.wait_group 1;" ::: "memory");
            else             asm volatile("cp.async.wait_group 0;" ::: "memory");
            __syncthreads();
            #pragma unroll
            for (int kk = 0; kk < 2; ++kk) {
                int kc = q * 2 + kk;
                uint4 U0 = *(const uint4*)(smem + SH_OFF + brow * SH_STRIDE + kc * 64 + tq * 16);
                uint4 U1 = *(const uint4*)(smem + SH_OFF + (brow + 8) * SH_STRIDE + kc * 64 + tq * 16);
                #pragma unroll
                for (int np = 0; np < 4; ++np) {
                    uint4 bf = sWf[((kc << 3) + nthalf * 4 + np) * 32 + lane];
                    mma16(acc[np], U0.x, U1.x, U0.z, U1.z, bf.x, bf.y);
                    mma16(acc[np], U0.y, U1.y, U0.w, U1.w, bf.x, bf.y);
                    mma16(acc[np], U0.x, U1.x, U0.z, U1.z, bf.z, bf.w);
                }
            }
        }

        #pragma unroll
        for (int np = 0; np < 4; ++np) {
            *(float2*)(part_row0 + np * 8)          = make_float2(acc[np][0], acc[np][1]);
            *(float2*)(part_row0 + 8 * DH + np * 8) = make_float2(acc[np][2], acc[np][3]);
        }

        grid_barrier(gen);

        // ---- phase 2: reduce 8 partials + xW + bias, tanh -> g_H2 ----
        {
            float2 s = Cp2[gtid];
            #pragma unroll
            for (int sp = 1; sp < KSPLIT; ++sp) {
                float2 c = Cp2[sp * 65536 + gtid];
                s.x += c.x; s.y += c.y;
            }
            float rx = tanhf(s.x + xw_pre.x + bias.x);
            float ry = tanhf(s.y + xw_pre.y + bias.y);

            float hx = bf16of(rx), hy = bf16of(ry);
            h2w[0] = bf16pair(hx, hy);
            h2w[1] = bf16pair(rx - hx, ry - hy);

            if (t == SEQ - 1) ((float2*)g_H)[gtid] = make_float2(rx, ry);
        }

        grid_barrier(gen);
    }

    // ------------------- Epilogue: logits + softmax -------------------
    {
        float* sv   = (float*)smem;
        float* sred = (float*)smem + 1024;
        const int b = blk;

        if (tid < 256)
            ((float4*)sv)[tid] = *(const float4*)&g_H[b * DH + (tid << 2)];
        __syncthreads();

        float logit = 0.f, e = 0.f;
        if (tid < 256) {
            float acc = 0.f;
            const float4* wr = (const float4*)(Wh2o + tid * DH);
            #pragma unroll 8
            for (int qq = 0; qq < DH / 4; ++qq) {
                float4 w = wr[qq];
                float4 h = ((const float4*)sv)[qq];
                acc += w.x * h.x + w.y * h.y + w.z * h.z + w.w * h.w;
            }
            logit = acc + bh2o[tid];
            sred[tid] = logit;
        }
        __syncthreads();
        for (int s = 128; s > 0; s >>= 1) {
            if (tid < s) sred[tid] = fmaxf(sred[tid], sred[tid + s]);
            __syncthreads();
        }
        float mx = sred[0];
        __syncthreads();
        if (tid < 256) {
            e = expf(logit - mx);
            sred[tid] = e;
        }
        __syncthreads();
        for (int s = 128; s > 0; s >>= 1) {
            if (tid < s) sred[tid] += sred[tid + s];
            __syncthreads();
        }
        if (tid < 256) {
            float inv = 1.f / sred[0];
            out[b * DOUT + tid] = e * inv;
        }
    }

    if (out_size >= BATCH * DOUT + BATCH * DH) {
        for (int i = gtid; i < BATCH * DH; i += NBLK * NTHR)
            out[BATCH * DOUT + i] = g_H[i];
    }
}

// ---------------------------------------------------------------------------
extern "C" void kernel_launch(void* const* d_in, const int* in_sizes, int n_in,
                              void* d_out, int out_size)
{
    const float* x      = (const float*)d_in[0];
    const float* hidden = (const float*)d_in[1];
    const float* Wi2h   = (const float*)d_in[2];
    const float* bi2h   = (const float*)d_in[3];
    const float* Wh2o   = (const float*)d_in[4];
    const float* bh2o   = (const float*)d_in[5];
    float* out = (float*)d_out;

    cudaFuncSetAttribute(k_rnn, cudaFuncAttributeMaxDynamicSharedMemorySize,
                         SMEM_RNN);
    cudaFuncSetAttribute(k_xw_mma, cudaFuncAttributeMaxDynamicSharedMemorySize,
                         SMEM_XW);

    k_init<<<512, 256>>>(hidden);

    long prep_items = A_PAIRS + (long)DH * 256;
    k_prep<<<(int)((prep_items + 255) / 256), 256>>>(x, Wi2h);

    dim3 gx(DH / 128, MTOT / 128);   // (8, 512)
    k_xw_mma<<<gx, 256, SMEM_XW>>>();

    k_rnn<<<NBLK, NTHR, SMEM_RNN>>>(Wi2h, bi2h, Wh2o, bh2o, out, out_size);
}